// round 12
// baseline (speedup 1.0000x reference)
#include <cuda_runtime.h>
#include <math.h>

#define NQ 14
#define NSTATE (1 << NQ)          // 16384 amplitudes
#define THREADS 1024
#define NWARP (THREADS / 32)

// ---------------------------------------------------------------------------
// Compile-time circuit structure. The CNOT rings are a fixed GF(2)-linear map
// L on basis labels; after l rings the label map is M_l = L^l. A 1-qubit gate
// on logical qubit q (applied after l rings, tracked lazily) pairs physical
// indices p, p^d where d = col_q(M_l^{-1}); logical bit value = parity(row_q(M_l)&p).
// All of this is input-independent -> constexpr.
// ---------------------------------------------------------------------------

struct PassT {
    unsigned vec[11];    // basis: tid bits 0..9 (+ k-bit at [10] for 3q passes)
    unsigned offs[16];   // member XOR offsets (subset-XOR of the group's d's)
};
struct AllData {
    PassT pass[8];
    unsigned ro[NQ];     // readout Z-sign parity masks (rows of M_3)
    int rocode[NQ];      // Walsh coefficient index per qubit (final pass)
};

constexpr int cpopc(unsigned x) { int c = 0; while (x) { c += (int)(x & 1u); x >>= 1; } return c; }

constexpr AllData build_data() {
    AllData A{};
    unsigned dmask[2][NQ] = {}, mmask[2][NQ] = {}, ro[NQ] = {};
    {
        unsigned row[NQ] = {}, col[NQ] = {};
        for (int q = 0; q < NQ; q++) { row[q] = 1u << q; col[q] = 1u << q; }
        for (int step = 1; step <= 3; ++step) {
            unsigned nr[NQ] = {}, nc[NQ] = {};
            unsigned all = 0;
            for (int q = 0; q < NQ; q++) all ^= row[q];
            nr[0] = all ^ row[0];
            unsigned pref = row[0];
            for (int k = 1; k < NQ; k++) { pref ^= row[k]; nr[k] = pref; }
            nc[0] = col[0] ^ col[1];
            for (int q = 1; q < NQ - 1; q++) nc[q] = col[q] ^ col[q + 1];
            nc[NQ - 1] = col[0] ^ col[1] ^ col[NQ - 1];
            for (int q = 0; q < NQ; q++) { row[q] = nr[q]; col[q] = nc[q]; }
            if (step < 3)
                for (int q = 0; q < NQ; q++) { dmask[step - 1][q] = col[q]; mmask[step - 1][q] = row[q]; }
            else
                for (int q = 0; q < NQ; q++) ro[q] = row[q];
        }
    }
    for (int q = 0; q < NQ; q++) A.ro[q] = ro[q];

    for (int pi = 0; pi < 8; pi++) {
        const int L = pi / 4, G = pi % 4;
        const int ngq = (G < 2) ? 4 : 3;            // groups (4,4,3,3), qubits {G+4r}
        unsigned d[4] = {}, m[4] = {};
        for (int r = 0; r < ngq; r++) { int q = G + 4 * r; d[r] = dmask[L][q]; m[r] = mmask[L][q]; }
        for (int i = 0; i < (1 << ngq); i++) {
            unsigned o = 0;
            for (int r = 0; r < ngq; r++) if ((i >> r) & 1) o ^= d[r];
            A.pass[pi].offs[i] = o;
        }
        // pivots of span{d}
        unsigned red[4] = {}; int piv[4] = {};
        unsigned pivmask = 0;
        for (int r = 0; r < ngq; r++) {
            unsigned v = d[r];
            for (int h = 0; h < r; h++) if ((v >> piv[h]) & 1u) v ^= red[h];
            int pb = 0; while (!((v >> pb) & 1u)) pb++;
            piv[r] = pb; red[r] = v; pivmask |= 1u << pb;
        }
        // basis of the logical-zero subspace Z (coset representatives):
        // P(e_b) = e_b ^ sum_r [bit b of m_r] d_r for non-pivot b
        unsigned w[11] = {}; int nz = 0;
        for (int b = 0; b < NQ; b++) {
            if ((pivmask >> b) & 1u) continue;
            unsigned p = 1u << b;
            for (int r = 0; r < ngq; r++) if ((m[r] >> b) & 1u) p ^= d[r];
            w[nz++] = p;
        }
        // Recombine (invertible row ops) so vec[t] for t=0..3 has low4 == (1<<t)
        // and every other vector has low4 == 0  =>  within a warp, lane bits 0..3
        // map identically onto smem index bits 0..3: all LDS.64/STS.64 conflict-free.
        int pos = 0;
        for (int t = 0; t < 4; t++) {
            int f = -1;
            for (int i = pos; i < nz; i++) if ((w[i] >> t) & 1u) { f = i; break; }
            if (f < 0) continue;
            unsigned tmp = w[pos]; w[pos] = w[f]; w[f] = tmp;
            for (int i = 0; i < nz; i++) if (i != pos && ((w[i] >> t) & 1u)) w[i] ^= w[pos];
            pos++;
        }
        for (int i = 0; i < nz; i++) A.pass[pi].vec[i] = w[i];
    }
    // Walsh coefficient index for the final pass (L=1, G=3; qubits {3,7,11})
    for (int q = 0; q < NQ; q++) {
        int c = 0;
        for (int r = 0; r < 3; r++)
            c |= (cpopc(ro[q] & dmask[1][3 + 4 * r]) & 1) << r;
        A.rocode[q] = c;
    }
    return A;
}

__device__ constexpr AllData AD = build_data();

struct SmallSmem {
    float2 u[NQ][2];              // RX(w0)*RY(theta)|0> per qubit
    float2 Tlow[64];              // product table, qubits 0..5
    float2 Thigh[256];            // product table, qubits 6..13
    float wc[2][NQ], ws[2][NQ];   // cos/sin(w/2), layers 1,2
    float red[NWARP][NQ];
};

__device__ __forceinline__ float2 cmulf(float2 a, float2 b) {
    return make_float2(a.x * b.x - a.y * b.y, a.x * b.y + a.y * b.x);
}

// ---- fused multi-qubit RX pass; all masks are immediates -------------------
template<int PI, int NGQ, int KG, bool FIRST>
__device__ __forceinline__ void do_pass(float2* __restrict__ S, SmallSmem& sm, int tid)
{
    constexpr int L = PI / 4, G = PI % 4;
    constexpr int NM = 1 << NGQ;

    float cs[NGQ], sn[NGQ];
#pragma unroll
    for (int r = 0; r < NGQ; r++) { cs[r] = sm.wc[L][G + 4 * r]; sn[r] = sm.ws[L][G + 4 * r]; }

    unsigned pb0 = 0;
#pragma unroll
    for (int j = 0; j < 10; j++)
        if ((tid >> j) & 1) pb0 ^= AD.pass[PI].vec[j];

    __syncthreads();   // previous pass stores -> this pass loads

    float2 A[KG][NM];
#pragma unroll
    for (int kg = 0; kg < KG; kg++) {
        const unsigned pb = kg ? (pb0 ^ AD.pass[PI].vec[10]) : pb0;
#pragma unroll
        for (int i = 0; i < NM; i++) {
            const unsigned p = pb ^ AD.pass[PI].offs[i];   // immediate XOR, independent
            if (FIRST) A[kg][i] = cmulf(sm.Tlow[p & 63], sm.Thigh[p >> 6]);
            else       A[kg][i] = S[p];
        }
    }
#pragma unroll
    for (int r = 0; r < NGQ; r++) {
        const float c = cs[r], s = sn[r];
#pragma unroll
        for (int kg = 0; kg < KG; kg++) {
#pragma unroll
            for (int i = 0; i < NM; i++) {
                if (i & (1 << r)) continue;
                const int j = i | (1 << r);
                float2 a = A[kg][i], b = A[kg][j];
                A[kg][i].x = c * a.x + s * b.y;  A[kg][i].y = c * a.y - s * b.x;
                A[kg][j].x = s * a.y + c * b.x;  A[kg][j].y = -s * a.x + c * b.y;
            }
        }
    }
#pragma unroll
    for (int kg = 0; kg < KG; kg++) {
        const unsigned pb = kg ? (pb0 ^ AD.pass[PI].vec[10]) : pb0;
#pragma unroll
        for (int i = 0; i < NM; i++)
            S[pb ^ AD.pass[PI].offs[i]] = A[kg][i];
    }
}

// ---- final pass (PI=7, 3q, KG=2): fold readout, skip the state store -------
__device__ __forceinline__ void do_last(const float2* __restrict__ S, SmallSmem& sm,
                                        int tid, float* acc)
{
    constexpr int PI = 7, NGQ = 3, NM = 8;
    float cs[NGQ], sn[NGQ];
#pragma unroll
    for (int r = 0; r < NGQ; r++) { cs[r] = sm.wc[1][3 + 4 * r]; sn[r] = sm.ws[1][3 + 4 * r]; }

    unsigned pb0 = 0;
#pragma unroll
    for (int j = 0; j < 10; j++)
        if ((tid >> j) & 1) pb0 ^= AD.pass[PI].vec[j];

    __syncthreads();

#pragma unroll
    for (int kg = 0; kg < 2; kg++) {
        const unsigned pb = kg ? (pb0 ^ AD.pass[PI].vec[10]) : pb0;
        float2 A[NM];
#pragma unroll
        for (int i = 0; i < NM; i++)
            A[i] = S[pb ^ AD.pass[PI].offs[i]];
#pragma unroll
        for (int r = 0; r < NGQ; r++) {
            const float c = cs[r], s = sn[r];
#pragma unroll
            for (int i = 0; i < NM; i++) {
                if (i & (1 << r)) continue;
                const int j = i | (1 << r);
                float2 a = A[i], b = A[j];
                A[i].x = c * a.x + s * b.y;  A[i].y = c * a.y - s * b.x;
                A[j].x = s * a.y + c * b.x;  A[j].y = -s * a.x + c * b.y;
            }
        }
        float pr[NM];
#pragma unroll
        for (int i = 0; i < NM; i++) pr[i] = A[i].x * A[i].x + A[i].y * A[i].y;
#pragma unroll
        for (int r = 0; r < NGQ; r++) {
#pragma unroll
            for (int i = 0; i < NM; i++) {
                if (i & (1 << r)) continue;
                const int j = i | (1 << r);
                float u2 = pr[i], v2 = pr[j];
                pr[i] = u2 + v2; pr[j] = u2 - v2;
            }
        }
#pragma unroll
        for (int q = 0; q < NQ; q++) {
            const float v = pr[AD.rocode[q]];                  // constexpr index
            const unsigned sgn = (unsigned)(__popc(AD.ro[q] & pb) & 1) << 31;
            acc[q] += __uint_as_float(__float_as_uint(v) ^ sgn);
        }
    }
}

__global__ __launch_bounds__(THREADS, 1)
void qsim_kernel(const float* __restrict__ xin,
                 const float* __restrict__ win,
                 float* __restrict__ out)
{
    extern __shared__ float2 S[];           // 16384 complex amplitudes (131072 B)
    __shared__ SmallSmem sm;

    const int tid = threadIdx.x;
    const int samp = blockIdx.x;

    // ---------------- setup stage 1: angles ----------------
    if (tid < NQ) {
        float th = tanhf(xin[samp * NQ + tid]) * 1.57079632679489662f; // tanh(x)*pi/2
        float c, s;
        sincosf(th, &s, &c);
        float hw = win[tid] * 0.5f;
        float sw, cw;
        sincosf(hw, &sw, &cw);
        sm.u[tid][0] = make_float2(cw * c, -sw * s);
        sm.u[tid][1] = make_float2(cw * s, -sw * c);
    }
    if (tid >= 64 && tid < 64 + 2 * NQ) {
        int l = (tid - 64) / NQ, q = (tid - 64) % NQ;
        float hw = win[(l + 1) * NQ + q] * 0.5f;
        float sw, cw;
        sincosf(hw, &sw, &cw);
        sm.wc[l][q] = cw;
        sm.ws[l][q] = sw;
    }
    __syncthreads();

    // ---------------- setup stage 2: product tables ----------------
    if (tid < 64) {
        float2 v = sm.u[0][tid & 1];
#pragma unroll
        for (int q = 1; q < 6; q++) v = cmulf(v, sm.u[q][(tid >> q) & 1]);
        sm.Tlow[tid] = v;
    }
    if (tid >= 128 && tid < 384) {
        int t = tid - 128;
        float2 v = sm.u[6][t & 1];
#pragma unroll
        for (int q = 1; q < 8; q++) v = cmulf(v, sm.u[6 + q][(t >> q) & 1]);
        sm.Thigh[t] = v;
    }

    // ---------------- 8 fused passes; init folded into pass 0 ----------------
    do_pass<0, 4, 1, true >(S, sm, tid);
    do_pass<1, 4, 1, false>(S, sm, tid);
    do_pass<2, 3, 2, false>(S, sm, tid);
    do_pass<3, 3, 2, false>(S, sm, tid);
    do_pass<4, 4, 1, false>(S, sm, tid);
    do_pass<5, 4, 1, false>(S, sm, tid);
    do_pass<6, 3, 2, false>(S, sm, tid);

    float acc[NQ];
#pragma unroll
    for (int q = 0; q < NQ; q++) acc[q] = 0.0f;
    do_last(S, sm, tid, acc);

    // ---------------- block reduction of <Z_q> ----------------
#pragma unroll
    for (int q = 0; q < NQ; q++) {
#pragma unroll
        for (int off = 16; off; off >>= 1)
            acc[q] += __shfl_xor_sync(0xffffffffu, acc[q], off);
    }
    const int wid = tid >> 5, lane = tid & 31;
    if (lane == 0) {
#pragma unroll
        for (int q = 0; q < NQ; q++) sm.red[wid][q] = acc[q];
    }
    __syncthreads();
    if (tid < NQ) {
        float r = 0.0f;
#pragma unroll
        for (int w = 0; w < NWARP; w++) r += sm.red[w][tid];
        out[samp * NQ + tid] = r;
    }
}

extern "C" void kernel_launch(void* const* d_in, const int* in_sizes, int n_in,
                              void* d_out, int out_size)
{
    const float* x = (const float*)d_in[0];
    const float* w = (const float*)d_in[1];
    if (n_in >= 2 && in_sizes[0] == 3 * NQ && in_sizes[1] != 3 * NQ) {
        // defensive: inputs arrived as (weights, x)
        const float* tmp = x; x = w; w = tmp;
    }
    const int batch = out_size / NQ;

    cudaFuncSetAttribute(qsim_kernel,
                         cudaFuncAttributeMaxDynamicSharedMemorySize,
                         NSTATE * (int)sizeof(float2));

    qsim_kernel<<<batch, THREADS, NSTATE * sizeof(float2)>>>(x, w, (float*)d_out);
}

// round 17
// speedup vs baseline: 1.7240x; 1.7240x over previous
#include <cuda_runtime.h>
#include <math.h>

#define NQ 14
#define NSTATE (1 << NQ)          // 16384 amplitudes
#define THREADS 512
#define NWARP (THREADS / 32)

// ---------------------------------------------------------------------------
// Compile-time circuit structure. The CNOT rings are a fixed GF(2)-linear map
// L on basis labels; after l rings the label map is M_l = L^l. A 1-qubit gate
// on logical qubit q (applied lazily) pairs physical indices p, p^d where
// d = col_q(M_l^{-1}); logical bit value = parity(row_q(M_l) & p).
// All input-independent -> constexpr immediates in SASS.
// ---------------------------------------------------------------------------

struct PassT {
    unsigned vec[11];    // basis: tid bits 0..8, then k bits (up to 2)
    unsigned offs[16];   // member XOR offsets (subset-XOR of the group's d's)
};
struct AllData {
    PassT pass[8];
    unsigned ro[NQ];     // readout Z-sign parity masks (rows of M_3)
    int rocode[NQ];      // Walsh coefficient index per qubit (final pass)
};

constexpr int cpopc(unsigned x) { int c = 0; while (x) { c += (int)(x & 1u); x >>= 1; } return c; }

constexpr AllData build_data() {
    AllData A{};
    unsigned dmask[2][NQ] = {}, mmask[2][NQ] = {}, ro[NQ] = {};
    {
        unsigned row[NQ] = {}, col[NQ] = {};
        for (int q = 0; q < NQ; q++) { row[q] = 1u << q; col[q] = 1u << q; }
        for (int step = 1; step <= 3; ++step) {
            unsigned nr[NQ] = {}, nc[NQ] = {};
            unsigned all = 0;
            for (int q = 0; q < NQ; q++) all ^= row[q];
            nr[0] = all ^ row[0];
            unsigned pref = row[0];
            for (int k = 1; k < NQ; k++) { pref ^= row[k]; nr[k] = pref; }
            nc[0] = col[0] ^ col[1];
            for (int q = 1; q < NQ - 1; q++) nc[q] = col[q] ^ col[q + 1];
            nc[NQ - 1] = col[0] ^ col[1] ^ col[NQ - 1];
            for (int q = 0; q < NQ; q++) { row[q] = nr[q]; col[q] = nc[q]; }
            if (step < 3)
                for (int q = 0; q < NQ; q++) { dmask[step - 1][q] = col[q]; mmask[step - 1][q] = row[q]; }
            else
                for (int q = 0; q < NQ; q++) ro[q] = row[q];
        }
    }
    for (int q = 0; q < NQ; q++) A.ro[q] = ro[q];

    for (int pi = 0; pi < 8; pi++) {
        const int L = pi / 4, G = pi % 4;
        const int ngq = (G < 2) ? 4 : 3;            // groups (4,4,3,3), qubits {G+4r}
        unsigned d[4] = {}, m[4] = {};
        for (int r = 0; r < ngq; r++) { int q = G + 4 * r; d[r] = dmask[L][q]; m[r] = mmask[L][q]; }
        for (int i = 0; i < (1 << ngq); i++) {
            unsigned o = 0;
            for (int r = 0; r < ngq; r++) if ((i >> r) & 1) o ^= d[r];
            A.pass[pi].offs[i] = o;
        }
        // pivots of span{d}
        unsigned red[4] = {}; int piv[4] = {};
        unsigned pivmask = 0;
        for (int r = 0; r < ngq; r++) {
            unsigned v = d[r];
            for (int h = 0; h < r; h++) if ((v >> piv[h]) & 1u) v ^= red[h];
            int pb = 0; while (!((v >> pb) & 1u)) pb++;
            piv[r] = pb; red[r] = v; pivmask |= 1u << pb;
        }
        // coset-representative basis: P(e_b) = e_b ^ sum_r [bit b of m_r] d_r,
        // over non-pivot bits b (14 - ngq vectors).
        unsigned w[11] = {}; int nz = 0;
        for (int b = 0; b < NQ; b++) {
            if ((pivmask >> b) & 1u) continue;
            unsigned p = 1u << b;
            for (int r = 0; r < ngq; r++) if ((m[r] >> b) & 1u) p ^= d[r];
            w[nz++] = p;
        }
        // Recombine (invertible row ops) so vec[t], t=0..3, has low4 == (1<<t)
        // and all other vectors have low4 == 0. Then lane bits 0..3 map
        // identically to smem float2-index bits 0..3 => each 16-lane phase of
        // every LDS.64/STS.64 covers 16 distinct bank-pairs: conflict-free.
        int pos = 0;
        for (int t = 0; t < 4; t++) {
            int f = -1;
            for (int i = pos; i < nz; i++) if ((w[i] >> t) & 1u) { f = i; break; }
            if (f < 0) continue;
            unsigned tmp = w[pos]; w[pos] = w[f]; w[f] = tmp;
            for (int i = 0; i < nz; i++) if (i != pos && ((w[i] >> t) & 1u)) w[i] ^= w[pos];
            pos++;
        }
        for (int i = 0; i < nz; i++) A.pass[pi].vec[i] = w[i];
    }
    // Walsh coefficient index for the final pass (L=1, G=3; qubits {3,7,11})
    for (int q = 0; q < NQ; q++) {
        int c = 0;
        for (int r = 0; r < 3; r++)
            c |= (cpopc(ro[q] & dmask[1][3 + 4 * r]) & 1) << r;
        A.rocode[q] = c;
    }
    return A;
}

__device__ constexpr AllData AD = build_data();

struct SmallSmem {
    float2 u[NQ][2];              // RX(w0)*RY(theta)|0> per qubit
    float2 Tlow[64];              // product table, qubits 0..5
    float2 Thigh[256];            // product table, qubits 6..13
    float wc[2][NQ], ws[2][NQ];   // cos/sin(w/2), layers 1,2
    float red[NWARP][NQ];
};

__device__ __forceinline__ float2 cmulf(float2 a, float2 b) {
    return make_float2(a.x * b.x - a.y * b.y, a.x * b.y + a.y * b.x);
}

// ---- fused multi-qubit RX pass; all masks are immediates -------------------
// NM = 2^NGQ members per group, KG groups per thread (NM*KG == 32).
template<int PI, int NGQ, int KG, bool FIRST>
__device__ __forceinline__ void do_pass(float2* __restrict__ S, SmallSmem& sm, int tid)
{
    constexpr int L = PI / 4, G = PI % 4;
    constexpr int NM = 1 << NGQ;

    float cs[NGQ], sn[NGQ];
#pragma unroll
    for (int r = 0; r < NGQ; r++) { cs[r] = sm.wc[L][G + 4 * r]; sn[r] = sm.ws[L][G + 4 * r]; }

    unsigned pb0 = 0;
#pragma unroll
    for (int j = 0; j < 9; j++)
        if ((tid >> j) & 1) pb0 ^= AD.pass[PI].vec[j];

    __syncthreads();   // previous pass stores -> this pass loads

    float2 A[KG][NM];
    // batched independent loads across all groups (max MLP, no addr chains)
#pragma unroll
    for (int kg = 0; kg < KG; kg++) {
        unsigned pb = pb0;
        if (kg & 1) pb ^= AD.pass[PI].vec[9];
        if (KG > 2 && (kg & 2)) pb ^= AD.pass[PI].vec[10];
#pragma unroll
        for (int i = 0; i < NM; i++) {
            const unsigned p = pb ^ AD.pass[PI].offs[i];   // LOP3 with immediate
            if (FIRST) A[kg][i] = cmulf(sm.Tlow[p & 63], sm.Thigh[p >> 6]);
            else       A[kg][i] = S[p];
        }
    }
    // NGQ levels of RX butterflies: RX = [[c,-is],[-is,c]]
#pragma unroll
    for (int r = 0; r < NGQ; r++) {
        const float c = cs[r], s = sn[r];
#pragma unroll
        for (int kg = 0; kg < KG; kg++) {
#pragma unroll
            for (int i = 0; i < NM; i++) {
                if (i & (1 << r)) continue;
                const int j = i | (1 << r);
                float2 a = A[kg][i], b = A[kg][j];
                A[kg][i].x = c * a.x + s * b.y;  A[kg][i].y = c * a.y - s * b.x;
                A[kg][j].x = s * a.y + c * b.x;  A[kg][j].y = -s * a.x + c * b.y;
            }
        }
    }
#pragma unroll
    for (int kg = 0; kg < KG; kg++) {
        unsigned pb = pb0;
        if (kg & 1) pb ^= AD.pass[PI].vec[9];
        if (KG > 2 && (kg & 2)) pb ^= AD.pass[PI].vec[10];
#pragma unroll
        for (int i = 0; i < NM; i++)
            S[pb ^ AD.pass[PI].offs[i]] = A[kg][i];
    }
}

// ---- final pass (PI=7, 3q, KG=4): fold readout, skip the state store -------
__device__ __forceinline__ void do_last(const float2* __restrict__ S, SmallSmem& sm,
                                        int tid, float* acc)
{
    constexpr int PI = 7, NGQ = 3, NM = 8;
    float cs[NGQ], sn[NGQ];
#pragma unroll
    for (int r = 0; r < NGQ; r++) { cs[r] = sm.wc[1][3 + 4 * r]; sn[r] = sm.ws[1][3 + 4 * r]; }

    unsigned pb0 = 0;
#pragma unroll
    for (int j = 0; j < 9; j++)
        if ((tid >> j) & 1) pb0 ^= AD.pass[PI].vec[j];

    __syncthreads();

#pragma unroll 1
    for (int kg = 0; kg < 4; kg++) {
        unsigned pb = pb0;
        if (kg & 1) pb ^= AD.pass[PI].vec[9];
        if (kg & 2) pb ^= AD.pass[PI].vec[10];
        float2 A[NM];
#pragma unroll
        for (int i = 0; i < NM; i++)
            A[i] = S[pb ^ AD.pass[PI].offs[i]];
#pragma unroll
        for (int r = 0; r < NGQ; r++) {
            const float c = cs[r], s = sn[r];
#pragma unroll
            for (int i = 0; i < NM; i++) {
                if (i & (1 << r)) continue;
                const int j = i | (1 << r);
                float2 a = A[i], b = A[j];
                A[i].x = c * a.x + s * b.y;  A[i].y = c * a.y - s * b.x;
                A[j].x = s * a.y + c * b.x;  A[j].y = -s * a.x + c * b.y;
            }
        }
        float pr[NM];
#pragma unroll
        for (int i = 0; i < NM; i++) pr[i] = A[i].x * A[i].x + A[i].y * A[i].y;
#pragma unroll
        for (int r = 0; r < NGQ; r++) {
#pragma unroll
            for (int i = 0; i < NM; i++) {
                if (i & (1 << r)) continue;
                const int j = i | (1 << r);
                float u2 = pr[i], v2 = pr[j];
                pr[i] = u2 + v2; pr[j] = u2 - v2;
            }
        }
#pragma unroll
        for (int q = 0; q < NQ; q++) {
            const float v = pr[AD.rocode[q]];                  // constexpr index
            const unsigned sgn = (unsigned)(__popc(AD.ro[q] & pb) & 1) << 31;
            acc[q] += __uint_as_float(__float_as_uint(v) ^ sgn);
        }
    }
}

__global__ __launch_bounds__(THREADS, 1)
void qsim_kernel(const float* __restrict__ xin,
                 const float* __restrict__ win,
                 float* __restrict__ out)
{
    extern __shared__ float2 S[];           // 16384 complex amplitudes (131072 B)
    __shared__ SmallSmem sm;

    const int tid = threadIdx.x;
    const int samp = blockIdx.x;

    // ---------------- setup stage 1: angles ----------------
    if (tid < NQ) {
        float th = tanhf(xin[samp * NQ + tid]) * 1.57079632679489662f; // tanh(x)*pi/2
        float c, s;
        sincosf(th, &s, &c);
        float hw = win[tid] * 0.5f;
        float sw, cw;
        sincosf(hw, &sw, &cw);
        sm.u[tid][0] = make_float2(cw * c, -sw * s);
        sm.u[tid][1] = make_float2(cw * s, -sw * c);
    }
    if (tid >= 64 && tid < 64 + 2 * NQ) {
        int l = (tid - 64) / NQ, q = (tid - 64) % NQ;
        float hw = win[(l + 1) * NQ + q] * 0.5f;
        float sw, cw;
        sincosf(hw, &sw, &cw);
        sm.wc[l][q] = cw;
        sm.ws[l][q] = sw;
    }
    __syncthreads();

    // ---------------- setup stage 2: product tables ----------------
    if (tid < 64) {
        float2 v = sm.u[0][tid & 1];
#pragma unroll
        for (int q = 1; q < 6; q++) v = cmulf(v, sm.u[q][(tid >> q) & 1]);
        sm.Tlow[tid] = v;
    }
    if (tid >= 128 && tid < 384) {
        int t = tid - 128;
        float2 v = sm.u[6][t & 1];
#pragma unroll
        for (int q = 1; q < 8; q++) v = cmulf(v, sm.u[6 + q][(t >> q) & 1]);
        sm.Thigh[t] = v;
    }

    // ---------------- 8 fused passes; init folded into pass 0 ----------------
    do_pass<0, 4, 2, true >(S, sm, tid);
    do_pass<1, 4, 2, false>(S, sm, tid);
    do_pass<2, 3, 4, false>(S, sm, tid);
    do_pass<3, 3, 4, false>(S, sm, tid);
    do_pass<4, 4, 2, false>(S, sm, tid);
    do_pass<5, 4, 2, false>(S, sm, tid);
    do_pass<6, 3, 4, false>(S, sm, tid);

    float acc[NQ];
#pragma unroll
    for (int q = 0; q < NQ; q++) acc[q] = 0.0f;
    do_last(S, sm, tid, acc);

    // ---------------- block reduction of <Z_q> ----------------
#pragma unroll
    for (int q = 0; q < NQ; q++) {
#pragma unroll
        for (int off = 16; off; off >>= 1)
            acc[q] += __shfl_xor_sync(0xffffffffu, acc[q], off);
    }
    const int wid = tid >> 5, lane = tid & 31;
    if (lane == 0) {
#pragma unroll
        for (int q = 0; q < NQ; q++) sm.red[wid][q] = acc[q];
    }
    __syncthreads();
    if (tid < NQ) {
        float r = 0.0f;
#pragma unroll
        for (int w = 0; w < NWARP; w++) r += sm.red[w][tid];
        out[samp * NQ + tid] = r;
    }
}

extern "C" void kernel_launch(void* const* d_in, const int* in_sizes, int n_in,
                              void* d_out, int out_size)
{
    const float* x = (const float*)d_in[0];
    const float* w = (const float*)d_in[1];
    if (n_in >= 2 && in_sizes[0] == 3 * NQ && in_sizes[1] != 3 * NQ) {
        // defensive: inputs arrived as (weights, x)
        const float* tmp = x; x = w; w = tmp;
    }
    const int batch = out_size / NQ;

    cudaFuncSetAttribute(qsim_kernel,
                         cudaFuncAttributeMaxDynamicSharedMemorySize,
                         NSTATE * (int)sizeof(float2));

    qsim_kernel<<<batch, THREADS, NSTATE * sizeof(float2)>>>(x, w, (float*)d_out);
}